// round 1
// baseline (speedup 1.0000x reference)
#include <cuda_runtime.h>

#define BSZ 16
#define SR 16
#define IMW 2048
#define IMH 2048
#define NBX (IMW/BSZ)   // 128
#define NBY (IMH/BSZ)   // 128
#define RSTRIDE 50      // padded row stride in pairs (must be even for 16B alignment)
#define NTHREADS 160
#define NACTIVE 132     // 4 dx-groups x 33 dy

typedef unsigned long long ull;

__device__ __forceinline__ ull f2x_sub(ull a, ull b) {
    ull d; asm("sub.rn.f32x2 %0, %1, %2;" : "=l"(d) : "l"(a), "l"(b)); return d;
}
__device__ __forceinline__ ull f2x_add(ull a, ull b) {
    ull d; asm("add.rn.f32x2 %0, %1, %2;" : "=l"(d) : "l"(a), "l"(b)); return d;
}
__device__ __forceinline__ ull f2x_abs(ull a) {
    return a & 0x7FFFFFFF7FFFFFFFULL;
}
__device__ __forceinline__ ull umin64(ull a, ull b) { return b < a ? b : a; }

__global__ __launch_bounds__(NTHREADS, 3)
void me_sad_kernel(const float* __restrict__ cur,
                   const float* __restrict__ refF,
                   float* __restrict__ out)
{
    // ref window 48x48, stored as row-pairs: s_ref[prow*RSTRIDE+pc] = (ref[prow][pc], ref[prow+1][pc])
    __shared__ __align__(16) ull s_ref[47 * RSTRIDE];   // 18.4 KB
    __shared__ __align__(16) ull s_cur[8 * 16];          // cur as row-pairs (rows 2k,2k+1)
    __shared__ ull s_red[NTHREADS / 32];

    const int t  = threadIdx.x;
    const int bx = blockIdx.x;
    const int by = blockIdx.y;
    const int gx0 = bx * BSZ - SR;
    const int gy0 = by * BSZ - SR;

    // ---- load 48x48 padded ref window; each value feeds .lo of its pair-row and .hi of the one above
    float* fref = reinterpret_cast<float*>(s_ref);
    for (int i = t; i < 48 * 48; i += NTHREADS) {
        int pr = i / 48, pc = i - pr * 48;
        int gy = gy0 + pr, gx = gx0 + pc;
        float v = 0.0f;
        if ((unsigned)gy < (unsigned)IMH && (unsigned)gx < (unsigned)IMW)
            v = refF[gy * IMW + gx];
        if (pr < 47) fref[(pr * RSTRIDE + pc) * 2]           = v;  // .lo of pair pr
        if (pr >= 1) fref[((pr - 1) * RSTRIDE + pc) * 2 + 1] = v;  // .hi of pair pr-1
    }
    // ---- load 16x16 current block, packed as 8 row-pairs
    float* fcur = reinterpret_cast<float*>(s_cur);
    for (int i = t; i < 256; i += NTHREADS) {
        int r = i >> 4, c = i & 15;
        float v = cur[(by * BSZ + r) * IMW + bx * BSZ + c];
        fcur[((r >> 1) * 16 + c) * 2 + (r & 1)] = v;
    }
    __syncthreads();

    ull p = 0xFFFFFFFFFFFFFFFFULL;  // packed (sad_bits << 32) | order_key

    if (t < NACTIVE) {
        const int g   = t / 33;        // dx group: dx = 8g + j - 16, j in [0,8]
        const int dyi = t - g * 33;    // 0..32  (dy = dyi - 16)

        ull acc[9];
        #pragma unroll
        for (int j = 0; j < 9; j++) acc[j] = 0ULL;

        #pragma unroll 1
        for (int rp = 0; rp < 8; ++rp) {
            // current row-pair: 16 packed pairs
            ull c2[16];
            const ulonglong2* cp = reinterpret_cast<const ulonglong2*>(&s_cur[rp * 16]);
            #pragma unroll
            for (int k = 0; k < 8; k++) { ulonglong2 v = cp[k]; c2[2*k] = v.x; c2[2*k+1] = v.y; }

            // reference row-pair window: 24 packed pairs starting at pcol = 8g
            const int prow = rp * 2 + dyi;   // 0..46
            ull r2[24];
            const ulonglong2* rr = reinterpret_cast<const ulonglong2*>(&s_ref[prow * RSTRIDE + 8 * g]);
            #pragma unroll
            for (int k = 0; k < 12; k++) { ulonglong2 v = rr[k]; r2[2*k] = v.x; r2[2*k+1] = v.y; }

            #pragma unroll
            for (int j = 0; j < 9; j++) {
                ull a = acc[j];
                #pragma unroll
                for (int c = 0; c < 16; c++)
                    a = f2x_add(a, f2x_abs(f2x_sub(c2[c], r2[c + j])));
                acc[j] = a;
            }
        }

        // per-thread best (dx ascending within thread == canonical order for this dy)
        #pragma unroll
        for (int j = 0; j < 9; j++) {
            float lo = __uint_as_float((unsigned)(acc[j] & 0xFFFFFFFFu));
            float hi = __uint_as_float((unsigned)(acc[j] >> 32));
            float s = lo + hi;
            unsigned key = (unsigned)(dyi * 33 + 8 * g + j);   // dy-major, dx-minor order
            ull cand = ((ull)__float_as_uint(s) << 32) | (ull)key;
            p = umin64(p, cand);
        }
    }

    // warp reduction (u64 min == lexicographic (sad, earliest-offset) min; sad > 0 so float bit order is value order)
    #pragma unroll
    for (int o = 16; o > 0; o >>= 1) {
        ull q = __shfl_xor_sync(0xFFFFFFFFu, p, o);
        p = umin64(p, q);
    }
    if ((t & 31) == 0) s_red[t >> 5] = p;
    __syncthreads();

    if (t == 0) {
        ull best = s_red[0];
        #pragma unroll
        for (int w = 1; w < NTHREADS / 32; w++) best = umin64(best, s_red[w]);
        unsigned key = (unsigned)(best & 0xFFFFFFFFu);
        int dyi = key / 33;
        int dxi = key - dyi * 33;
        int b = by * NBX + bx;
        out[b]                 = (float)(dxi - SR);                  // motion_x
        out[NBX * NBY + b]     = (float)(dyi - SR);                  // motion_y
        out[2 * NBX * NBY + b] = __uint_as_float((unsigned)(best >> 32));  // min_sad
    }
}

extern "C" void kernel_launch(void* const* d_in, const int* in_sizes, int n_in,
                              void* d_out, int out_size)
{
    const float* cur  = (const float*)d_in[0];
    const float* refF = (const float*)d_in[1];
    float* out = (float*)d_out;
    dim3 grid(NBX, NBY);
    me_sad_kernel<<<grid, NTHREADS>>>(cur, refF, out);
}

// round 2
// speedup vs baseline: 1.1190x; 1.1190x over previous
#include <cuda_runtime.h>

#define BSZ 16
#define SR 16
#define IMW 2048
#define IMH 2048
#define NBX (IMW/BSZ)   // 128
#define NBY (IMH/BSZ)   // 128

#define BPC 2           // image blocks per CTA (horizontal)
#define WINW (BPC*BSZ + 2*SR)   // 64  ref window width
#define WINH (BSZ + 2*SR)       // 48  ref window height
#define RST 66          // ref row stride in pairs: 66*8=528 B, 528 % 128 == 16 -> conflict-free
#define NTHREADS 288    // 9 full warps
#define NITEMS 272      // 2 blocks x 4 dx-groups x 34 dy-slots

typedef unsigned long long ull;

__device__ __forceinline__ ull f2x_sub(ull a, ull b) {
    ull d; asm("sub.rn.f32x2 %0, %1, %2;" : "=l"(d) : "l"(a), "l"(b)); return d;
}
__device__ __forceinline__ ull f2x_add(ull a, ull b) {
    ull d; asm("add.rn.f32x2 %0, %1, %2;" : "=l"(d) : "l"(a), "l"(b)); return d;
}
__device__ __forceinline__ ull f2x_abs(ull a) {
    return a & 0x7FFFFFFF7FFFFFFFULL;
}
__device__ __forceinline__ ull umin64(ull a, ull b) { return b < a ? b : a; }

__global__ __launch_bounds__(NTHREADS, 2)
void me_sad_kernel(const float* __restrict__ cur,
                   const float* __restrict__ refF,
                   float* __restrict__ out)
{
    // ref window as row-pairs: s_ref[p*RST+c] = (ref[p][c], ref[p+1][c]), p in [0,47)
    __shared__ __align__(16) ull s_ref[47 * RST];          // 24.8 KB
    __shared__ __align__(16) ull s_cur[BPC * 8 * 16];      // 2 KB: per block, 8 row-pairs x 16 cols
    __shared__ ull s_red[NTHREADS];                        // 2.3 KB

    const int t  = threadIdx.x;
    const int cx = blockIdx.x;          // 0..63  (pair of image blocks)
    const int by = blockIdx.y;          // 0..127
    const int gx0 = cx * (BPC * BSZ) - SR;   // leftmost ref col of window
    const int gy0 = by * BSZ - SR;           // topmost ref row of window

    // ---- fill ref window (64x48), each value feeds .lo of pair-row p and .hi of pair-row p-1
    float* fref = reinterpret_cast<float*>(s_ref);
    for (int i = t; i < WINW * WINH; i += NTHREADS) {
        int pr = i / WINW, pc = i - pr * WINW;
        int gy = gy0 + pr, gx = gx0 + pc;
        float v = 0.0f;
        if ((unsigned)gy < (unsigned)IMH && (unsigned)gx < (unsigned)IMW)
            v = refF[gy * IMW + gx];
        if (pr < WINH - 1) fref[(pr * RST + pc) * 2]           = v;
        if (pr >= 1)       fref[((pr - 1) * RST + pc) * 2 + 1] = v;
    }
    // ---- fill current blocks (2 x 16x16) as row-pairs
    float* fcur = reinterpret_cast<float*>(s_cur);
    for (int i = t; i < BPC * 256; i += NTHREADS) {
        int b = i >> 8;
        int r = (i >> 4) & 15, c = i & 15;
        float v = cur[(by * BSZ + r) * IMW + (cx * BPC + b) * BSZ + c];
        fcur[(b * 128 + (r >> 1) * 16 + c) * 2 + (r & 1)] = v;
    }
    __syncthreads();

    // ---- work item: u = b*136 + g*34 + dyq  (dyq==33 duplicates dyi=32; pad threads dup item 271)
    const int u   = (t < NITEMS) ? t : (NITEMS - 1);
    const int b   = u / 136;
    const int v0  = u - b * 136;
    const int g   = v0 / 34;            // dx group: dx_index = 8g + j, j in [0,8]
    const int dyq = v0 - g * 34;
    const int dyi = (dyq < 33) ? dyq : 32;
    const int colbase = b * BSZ + 8 * g;   // window col of leftmost ref pair for this item

    ull acc[9];
    #pragma unroll
    for (int j = 0; j < 9; j++) acc[j] = 0ULL;

    #pragma unroll 1
    for (int rp = 0; rp < 8; ++rp) {
        ull c2[16];
        const ulonglong2* cp = reinterpret_cast<const ulonglong2*>(&s_cur[b * 128 + rp * 16]);
        #pragma unroll
        for (int k = 0; k < 8; k++) { ulonglong2 w = cp[k]; c2[2*k] = w.x; c2[2*k+1] = w.y; }

        const int prow = rp * 2 + dyi;   // 0..46
        ull r2[24];
        const ulonglong2* rr = reinterpret_cast<const ulonglong2*>(&s_ref[prow * RST + colbase]);
        #pragma unroll
        for (int k = 0; k < 12; k++) { ulonglong2 w = rr[k]; r2[2*k] = w.x; r2[2*k+1] = w.y; }

        #pragma unroll
        for (int j = 0; j < 9; j++) {
            ull a = acc[j];
            #pragma unroll
            for (int c = 0; c < 16; c++)
                a = f2x_add(a, f2x_abs(f2x_sub(c2[c], r2[c + j])));
            acc[j] = a;
        }
    }

    // per-thread best, packed as (sad_bits << 32) | order_key  (u64 min == correct tie rule)
    ull p = 0xFFFFFFFFFFFFFFFFULL;
    #pragma unroll
    for (int j = 0; j < 9; j++) {
        float lo = __uint_as_float((unsigned)(acc[j] & 0xFFFFFFFFu));
        float hi = __uint_as_float((unsigned)(acc[j] >> 32));
        float s = lo + hi;
        unsigned key = (unsigned)(dyi * 33 + 8 * g + j);   // dy-major, dx-minor canonical order
        ull cand = ((ull)__float_as_uint(s) << 32) | (ull)key;
        p = umin64(p, cand);
    }
    s_red[t] = p;
    __syncthreads();

    // ---- per-block reduction: warp 0 -> block b=0, warp 1 -> block b=1
    if (t < 64) {
        const int rb = t >> 5;          // which of the 2 image blocks
        const int l  = t & 31;
        const int base = rb * 136;
        ull best = s_red[base + l];
        best = umin64(best, s_red[base + l + 32]);
        best = umin64(best, s_red[base + l + 64]);
        best = umin64(best, s_red[base + l + 96]);
        if (l < 8) best = umin64(best, s_red[base + l + 128]);
        #pragma unroll
        for (int o = 16; o > 0; o >>= 1) {
            ull q = __shfl_xor_sync(0xFFFFFFFFu, best, o);
            best = umin64(best, q);
        }
        if (l == 0) {
            unsigned key = (unsigned)(best & 0xFFFFFFFFu);
            int dyi_b = key / 33;
            int dxi_b = key - dyi_b * 33;
            int bg = by * NBX + cx * BPC + rb;
            out[bg]                 = (float)(dxi_b - SR);
            out[NBX * NBY + bg]     = (float)(dyi_b - SR);
            out[2 * NBX * NBY + bg] = __uint_as_float((unsigned)(best >> 32));
        }
    }
}

extern "C" void kernel_launch(void* const* d_in, const int* in_sizes, int n_in,
                              void* d_out, int out_size)
{
    const float* c  = (const float*)d_in[0];
    const float* r  = (const float*)d_in[1];
    float* out = (float*)d_out;
    dim3 grid(NBX / BPC, NBY);
    me_sad_kernel<<<grid, NTHREADS>>>(c, r, out);
}